// round 1
// baseline (speedup 1.0000x reference)
#include <cuda_runtime.h>
#include <math.h>

// Problem constants
#define B_    4096
#define DIN_  2048
#define DOUT_ 128
#define N_    8192   // 2*B_

// Scratch (device globals -- no allocation allowed)
__device__ float g_zn[N_ * DOUT_];        // normalized reps, 4 MB (L2-resident)
__device__ float g_rowsum_part[4 * N_];   // per-jsplit partial exp-row-sums
__device__ float g_pos[N_];               // positive-pair logits

// ---------------------------------------------------------------------------
// Kernel 1: H = relu(Z) @ W^T + b, then row-normalize -> g_zn
// Block = 256 threads computes a 64(row) x 128(col) output tile.
// Thread (tx,ty), tx=tid&15, ty=tid>>4: rows {ty+16r}, cols {tx+16c} (strided
// blocking => B-operand LDS hits 16 distinct banks; A-operand is broadcast).
// Smem tiles row-major with odd stride 33 (k-chunk 32) => conflict-free.
// ---------------------------------------------------------------------------
__global__ __launch_bounds__(256) void gemm1_norm_kernel(
    const float* __restrict__ zi, const float* __restrict__ zj,
    const float* __restrict__ W, const float* __restrict__ bias)
{
    __shared__ float As[64 * 33];    // 8448 B
    __shared__ float Bs[128 * 33];   // 16896 B

    const int tid = threadIdx.x;
    const int tx = tid & 15;
    const int ty = tid >> 4;
    const int i0 = blockIdx.x * 64;

    const float* Z = (i0 < B_) ? zi : zj;
    const int zr0 = (i0 < B_) ? i0 : (i0 - B_);

    float acc[4][8];
#pragma unroll
    for (int r = 0; r < 4; r++)
#pragma unroll
        for (int c = 0; c < 8; c++) acc[r][c] = 0.0f;

    for (int kc = 0; kc < DIN_; kc += 32) {
        // Load A chunk (64 rows x 32 k) with ReLU. 512 float4, 2 per thread.
#pragma unroll
        for (int it = 0; it < 2; it++) {
            int e = tid + it * 256;
            int r = e >> 3, f = e & 7;
            float4 v = *(const float4*)&Z[(size_t)(zr0 + r) * DIN_ + kc + 4 * f];
            v.x = fmaxf(v.x, 0.0f); v.y = fmaxf(v.y, 0.0f);
            v.z = fmaxf(v.z, 0.0f); v.w = fmaxf(v.w, 0.0f);
            float* p = &As[r * 33 + 4 * f];
            p[0] = v.x; p[1] = v.y; p[2] = v.z; p[3] = v.w;
        }
        // Load W chunk (128 rows x 32 k). 1024 float4, 4 per thread.
#pragma unroll
        for (int it = 0; it < 4; it++) {
            int e = tid + it * 256;
            int r = e >> 3, f = e & 7;
            float4 v = *(const float4*)&W[(size_t)r * DIN_ + kc + 4 * f];
            float* p = &Bs[r * 33 + 4 * f];
            p[0] = v.x; p[1] = v.y; p[2] = v.z; p[3] = v.w;
        }
        __syncthreads();

#pragma unroll 8
        for (int k = 0; k < 32; k++) {
            float a[4], bb[8];
#pragma unroll
            for (int r = 0; r < 4; r++) a[r] = As[(ty + 16 * r) * 33 + k];
#pragma unroll
            for (int c = 0; c < 8; c++) bb[c] = Bs[(tx + 16 * c) * 33 + k];
#pragma unroll
            for (int r = 0; r < 4; r++)
#pragma unroll
                for (int c = 0; c < 8; c++) acc[r][c] += a[r] * bb[c];
        }
        __syncthreads();
    }

    // Epilogue: +bias, row L2 norm (warp shfl across the 16 tx lanes), write zn
    float bv[8];
#pragma unroll
    for (int c = 0; c < 8; c++) bv[c] = bias[tx + 16 * c];

#pragma unroll
    for (int r = 0; r < 4; r++) {
        float h[8];
        float ss = 0.0f;
#pragma unroll
        for (int c = 0; c < 8; c++) {
            h[c] = acc[r][c] + bv[c];
            ss += h[c] * h[c];
        }
#pragma unroll
        for (int m = 1; m < 16; m <<= 1)
            ss += __shfl_xor_sync(0xffffffffu, ss, m);
        float inv = 1.0f / fmaxf(sqrtf(ss), 1e-8f);
        int gi = i0 + ty + 16 * r;
#pragma unroll
        for (int c = 0; c < 8; c++)
            g_zn[(size_t)gi * DOUT_ + tx + 16 * c] = h[c] * inv;
    }
}

// ---------------------------------------------------------------------------
// Kernel 2: for each row i, accumulate sum_{j != i} exp(2 * zn_i . zn_j),
// and capture pos_i = 2 * zn_i . zn_{(i+B) mod N}.
// Grid (128, 4): blockIdx.x -> 64-row i-tile, blockIdx.y -> 2048-col j-split.
// Per j-tile (64 cols), k=128 done in 2 chunks of 64 (smem fits 48KB static).
// Strided 4x4 register blocking, odd smem stride 65 => conflict-free LDS.
// ---------------------------------------------------------------------------
__global__ __launch_bounds__(256) void sim_rowsum_kernel()
{
    __shared__ float As[64 * 65];    // 16640 B
    __shared__ float Bs[64 * 65];    // 16640 B

    const int tid = threadIdx.x;
    const int tx = tid & 15;
    const int ty = tid >> 4;
    const int i0 = blockIdx.x * 64;
    const int jbase = blockIdx.y * 2048;

    float rowacc[4] = {0.0f, 0.0f, 0.0f, 0.0f};

    for (int jt = 0; jt < 32; jt++) {
        const int j0 = jbase + jt * 64;

        float dot[4][4];
#pragma unroll
        for (int r = 0; r < 4; r++)
#pragma unroll
            for (int c = 0; c < 4; c++) dot[r][c] = 0.0f;

#pragma unroll
        for (int kc = 0; kc < 2; kc++) {
            // Load A (i-rows) and B (j-rows) 64x64 chunks. 1024 float4 each,
            // 4 per thread each. Coalesced global reads; STS conflict-free.
#pragma unroll
            for (int it = 0; it < 4; it++) {
                int e = tid + it * 256;
                int r = e >> 4, f = e & 15;
                float4 va = *(const float4*)&g_zn[(size_t)(i0 + r) * DOUT_ + kc * 64 + 4 * f];
                float* pa = &As[r * 65 + 4 * f];
                pa[0] = va.x; pa[1] = va.y; pa[2] = va.z; pa[3] = va.w;
                float4 vb = *(const float4*)&g_zn[(size_t)(j0 + r) * DOUT_ + kc * 64 + 4 * f];
                float* pb = &Bs[r * 65 + 4 * f];
                pb[0] = vb.x; pb[1] = vb.y; pb[2] = vb.z; pb[3] = vb.w;
            }
            __syncthreads();

#pragma unroll 16
            for (int k = 0; k < 64; k++) {
                float a[4], bb[4];
#pragma unroll
                for (int r = 0; r < 4; r++) a[r] = As[(ty + 16 * r) * 65 + k];
#pragma unroll
                for (int c = 0; c < 4; c++) bb[c] = Bs[(tx + 16 * c) * 65 + k];
#pragma unroll
                for (int r = 0; r < 4; r++)
#pragma unroll
                    for (int c = 0; c < 4; c++) dot[r][c] += a[r] * bb[c];
            }
            __syncthreads();
        }

        // Epilogue for this 64x64 tile: mask diag, exp-accumulate, grab pos
#pragma unroll
        for (int r = 0; r < 4; r++) {
            int gi = i0 + ty + 16 * r;
            int pj = (gi + B_) & (N_ - 1);
#pragma unroll
            for (int c = 0; c < 4; c++) {
                int gj = j0 + tx + 16 * c;
                float s = 2.0f * dot[r][c];      // /temperature (0.5)
                if (gj != gi) rowacc[r] += __expf(s);
                if (gj == pj) g_pos[gi] = s;     // unique writer per row
            }
        }
    }

    // Reduce rowacc across the 16 tx lanes (lanes of same ty half-warp)
#pragma unroll
    for (int r = 0; r < 4; r++) {
        float v = rowacc[r];
#pragma unroll
        for (int m = 1; m < 16; m <<= 1)
            v += __shfl_xor_sync(0xffffffffu, v, m);
        if (tx == 0) {
            int gi = i0 + ty + 16 * r;
            g_rowsum_part[blockIdx.y * N_ + gi] = v;
        }
    }
}

// ---------------------------------------------------------------------------
// Kernel 3: loss = mean_i( log(sum_parts) - pos_i )
// ---------------------------------------------------------------------------
__global__ __launch_bounds__(256) void finalize_kernel(float* __restrict__ out)
{
    __shared__ double red[256];
    const int tid = threadIdx.x;
    double acc = 0.0;
    for (int i = tid; i < N_; i += 256) {
        float rs = g_rowsum_part[i] + g_rowsum_part[N_ + i] +
                   g_rowsum_part[2 * N_ + i] + g_rowsum_part[3 * N_ + i];
        acc += (double)logf(rs) - (double)g_pos[i];
    }
    red[tid] = acc;
    __syncthreads();
    for (int s = 128; s > 0; s >>= 1) {
        if (tid < s) red[tid] += red[tid + s];
        __syncthreads();
    }
    if (tid == 0) out[0] = (float)(red[0] / (double)N_);
}

// ---------------------------------------------------------------------------
extern "C" void kernel_launch(void* const* d_in, const int* in_sizes, int n_in,
                              void* d_out, int out_size)
{
    const float* zi = (const float*)d_in[0];
    const float* zj = (const float*)d_in[1];
    const float* W  = (const float*)d_in[2];
    const float* b  = (const float*)d_in[3];
    float* out = (float*)d_out;

    gemm1_norm_kernel<<<128, 256>>>(zi, zj, W, b);
    sim_rowsum_kernel<<<dim3(128, 4), 256>>>();
    finalize_kernel<<<1, 256>>>(out);
}

// round 2
// speedup vs baseline: 6.0870x; 6.0870x over previous
#include <cuda_runtime.h>
#include <cuda_bf16.h>
#include <math.h>
#include <stdint.h>

// Problem constants
#define B_    4096
#define DIN_  2048
#define DOUT_ 128
#define N_    8192   // 2*B_

// Scratch (device globals -- no allocation allowed)
__device__ __nv_bfloat16 g_znb[N_ * DOUT_];   // normalized reps, bf16, 2 MB
__device__ float g_rowsum_part[32 * N_];      // per-(jsplit,warpcol) partial sums
__device__ float g_pos[N_];                   // positive-pair logits

__device__ __forceinline__ uint32_t sptr(const void* p) {
    return (uint32_t)__cvta_generic_to_shared(p);
}

__device__ __forceinline__ void ldsm_x4(uint32_t addr, uint32_t& r0, uint32_t& r1,
                                        uint32_t& r2, uint32_t& r3) {
    asm volatile("ldmatrix.sync.aligned.m8n8.x4.shared.b16 {%0,%1,%2,%3}, [%4];"
                 : "=r"(r0), "=r"(r1), "=r"(r2), "=r"(r3) : "r"(addr));
}

__device__ __forceinline__ void mma16816(float* c, const uint32_t* a, const uint32_t* b) {
    asm volatile(
        "mma.sync.aligned.m16n8k16.row.col.f32.bf16.bf16.f32 "
        "{%0,%1,%2,%3}, {%4,%5,%6,%7}, {%8,%9}, {%0,%1,%2,%3};"
        : "+f"(c[0]), "+f"(c[1]), "+f"(c[2]), "+f"(c[3])
        : "r"(a[0]), "r"(a[1]), "r"(a[2]), "r"(a[3]), "r"(b[0]), "r"(b[1]));
}

// ---------------------------------------------------------------------------
// Kernel 1: H = relu(Z) @ W^T + b (bf16 tensor-core), then row-normalize.
// Block 256 thr (8 warps, 1x8 over cols). Block tile 64 rows x 128 cols,
// k-chunks of 128. Smem: A[64][128k] 16KB + W[128][128k] 32KB (swizzled).
// ---------------------------------------------------------------------------
__global__ __launch_bounds__(256) void gemm1_norm_kernel(
    const float* __restrict__ zi, const float* __restrict__ zj,
    const float* __restrict__ W, const float* __restrict__ bias)
{
    __shared__ __align__(16) unsigned char smraw[49152];
    __nv_bfloat16* As = (__nv_bfloat16*)smraw;             // rows of 256B (16 chunks)
    __nv_bfloat16* Ws = (__nv_bfloat16*)(smraw + 16384);   // rows of 256B
    const uint32_t Abase = sptr(As);
    const uint32_t Wbase = sptr(Ws);

    const int tid = threadIdx.x;
    const int lane = tid & 31;
    const int warp = tid >> 5;       // wc: cols 16*warp .. +16
    const int i0 = blockIdx.x * 64;

    const float* Z = (i0 < B_) ? zi : zj;
    const int zr0 = (i0 < B_) ? i0 : (i0 - B_);

    float acc[4][2][4];
#pragma unroll
    for (int mt = 0; mt < 4; mt++)
#pragma unroll
        for (int nt = 0; nt < 2; nt++)
#pragma unroll
            for (int e = 0; e < 4; e++) acc[mt][nt][e] = 0.0f;

    for (int kc = 0; kc < 16; kc++) {  // k chunks of 128
        __syncthreads();
        // Load+convert A chunk: 64 rows x 128 k. 1024 items of 8 floats.
#pragma unroll
        for (int it = 0; it < 4; it++) {
            int e = tid + it * 256;
            int r = e >> 4, c = e & 15;
            const float* src = &Z[(size_t)(zr0 + r) * DIN_ + kc * 128 + c * 8];
            float4 v0 = *(const float4*)src;
            float4 v1 = *(const float4*)(src + 4);
            __nv_bfloat16 h[8];
            h[0] = __float2bfloat16(fmaxf(v0.x, 0.f));
            h[1] = __float2bfloat16(fmaxf(v0.y, 0.f));
            h[2] = __float2bfloat16(fmaxf(v0.z, 0.f));
            h[3] = __float2bfloat16(fmaxf(v0.w, 0.f));
            h[4] = __float2bfloat16(fmaxf(v1.x, 0.f));
            h[5] = __float2bfloat16(fmaxf(v1.y, 0.f));
            h[6] = __float2bfloat16(fmaxf(v1.z, 0.f));
            h[7] = __float2bfloat16(fmaxf(v1.w, 0.f));
            int cs = c ^ (r & 7);
            *(uint4*)((unsigned char*)As + r * 256 + cs * 16) = *(uint4*)h;
        }
        // Load+convert W chunk: 128 rows x 128 k. 2048 items.
#pragma unroll
        for (int it = 0; it < 8; it++) {
            int e = tid + it * 256;
            int r = e >> 4, c = e & 15;
            const float* src = &W[(size_t)r * DIN_ + kc * 128 + c * 8];
            float4 v0 = *(const float4*)src;
            float4 v1 = *(const float4*)(src + 4);
            __nv_bfloat16 h[8];
            h[0] = __float2bfloat16(v0.x); h[1] = __float2bfloat16(v0.y);
            h[2] = __float2bfloat16(v0.z); h[3] = __float2bfloat16(v0.w);
            h[4] = __float2bfloat16(v1.x); h[5] = __float2bfloat16(v1.y);
            h[6] = __float2bfloat16(v1.z); h[7] = __float2bfloat16(v1.w);
            int cs = c ^ (r & 7);
            *(uint4*)((unsigned char*)Ws + r * 256 + cs * 16) = *(uint4*)h;
        }
        __syncthreads();

#pragma unroll
        for (int s = 0; s < 8; s++) {  // 8 k-steps of 16 per chunk
            uint32_t a[4][4];
#pragma unroll
            for (int mt = 0; mt < 4; mt++) {
                int rloc = 16 * mt + (lane & 15);
                int ch = 2 * s + (lane >> 4);
                uint32_t ad = Abase + rloc * 256 + ((ch ^ (rloc & 7)) << 4);
                ldsm_x4(ad, a[mt][0], a[mt][1], a[mt][2], a[mt][3]);
            }
            uint32_t b[2][2];
            {
                int nloc = 16 * warp + (lane & 7) + ((lane >> 4) << 3);
                int ch = 2 * s + ((lane >> 3) & 1);
                uint32_t ad = Wbase + nloc * 256 + ((ch ^ (nloc & 7)) << 4);
                ldsm_x4(ad, b[0][0], b[0][1], b[1][0], b[1][1]);
            }
#pragma unroll
            for (int mt = 0; mt < 4; mt++)
#pragma unroll
                for (int nt = 0; nt < 2; nt++)
                    mma16816(acc[mt][nt], a[mt], b[nt]);
        }
    }

    // Epilogue: stage h = acc + bias into smem, then normalize rows.
    __syncthreads();
    float* hsm = (float*)smraw;  // [64][132]
    {
        float bcol[2][2];
#pragma unroll
        for (int nt = 0; nt < 2; nt++)
#pragma unroll
            for (int e2 = 0; e2 < 2; e2++)
                bcol[nt][e2] = __ldg(&bias[16 * warp + 8 * nt + 2 * (lane & 3) + e2]);
#pragma unroll
        for (int mt = 0; mt < 4; mt++)
#pragma unroll
            for (int nt = 0; nt < 2; nt++)
#pragma unroll
                for (int e = 0; e < 4; e++) {
                    int row = 16 * mt + (lane >> 2) + 8 * (e >> 1);
                    int col = 16 * warp + 8 * nt + 2 * (lane & 3) + (e & 1);
                    hsm[row * 132 + col] = acc[mt][nt][e] + bcol[nt][e & 1];
                }
    }
    __syncthreads();

    // Each warp normalizes 8 rows.
#pragma unroll
    for (int rr = 0; rr < 8; rr++) {
        int r = 8 * warp + rr;
        float v[4], ss = 0.0f;
#pragma unroll
        for (int q = 0; q < 4; q++) {
            v[q] = hsm[r * 132 + lane + 32 * q];
            ss += v[q] * v[q];
        }
#pragma unroll
        for (int m = 16; m > 0; m >>= 1)
            ss += __shfl_xor_sync(0xffffffffu, ss, m);
        float inv = 1.0f / fmaxf(sqrtf(ss), 1e-8f);
        int gi = i0 + r;
#pragma unroll
        for (int q = 0; q < 4; q++)
            g_znb[(size_t)gi * DOUT_ + lane + 32 * q] = __float2bfloat16(v[q] * inv);
    }
}

// ---------------------------------------------------------------------------
// Kernel 2: sim rowsums via bf16 MMA. Grid (64, 8): 128-row i-tile x 1024-col
// j-split (8 j-tiles of 128). Smem: A[128][128k] 32KB resident + B[128][64k]
// 16KB chunk. 8 warps as 2x4 (warp tile 64x32).
// ---------------------------------------------------------------------------
__global__ __launch_bounds__(256, 2) void sim_rowsum_kernel()
{
    __shared__ __align__(16) unsigned char smraw[49152];
    unsigned char* Asm = smraw;           // [128][256B] swizzled
    unsigned char* Bsm = smraw + 32768;   // [128][128B] swizzled
    const uint32_t Abase = sptr(Asm);
    const uint32_t Bbase = sptr(Bsm);

    const int tid = threadIdx.x;
    const int lane = tid & 31;
    const int warp = tid >> 5;
    const int wr = warp >> 2;      // 0-1: rows 64*wr
    const int wc = warp & 3;       // 0-3: cols 32*wc
    const int i0 = blockIdx.x * 128;
    const int jbase = blockIdx.y * 1024;

    // Load A tile once (128 rows x 128 k bf16 = 2048 16B-chunks)
#pragma unroll
    for (int it = 0; it < 8; it++) {
        int e = tid + it * 256;
        int r = e >> 4, c = e & 15;
        uint4 v = *(const uint4*)&g_znb[(size_t)(i0 + r) * DOUT_ + c * 8];
        int cs = c ^ (r & 7);
        *(uint4*)(Asm + r * 256 + cs * 16) = v;
    }

    float rowacc[8];
#pragma unroll
    for (int x = 0; x < 8; x++) rowacc[x] = 0.0f;

    for (int jt = 0; jt < 8; jt++) {
        const int j0 = jbase + jt * 128;

        float acc[4][4][4];
#pragma unroll
        for (int mt = 0; mt < 4; mt++)
#pragma unroll
            for (int nt = 0; nt < 4; nt++)
#pragma unroll
                for (int e = 0; e < 4; e++) acc[mt][nt][e] = 0.0f;

#pragma unroll
        for (int kc = 0; kc < 2; kc++) {
            __syncthreads();
            // Load B chunk: 128 rows x 64 k = 1024 16B-chunks
#pragma unroll
            for (int it = 0; it < 4; it++) {
                int e = tid + it * 256;
                int r = e >> 3, c = e & 7;
                uint4 v = *(const uint4*)&g_znb[(size_t)(j0 + r) * DOUT_ + kc * 64 + c * 8];
                int cs = c ^ (r & 7);
                *(uint4*)(Bsm + r * 128 + cs * 16) = v;
            }
            __syncthreads();

#pragma unroll
            for (int s2 = 0; s2 < 4; s2++) {
                int sg = kc * 4 + s2;  // global k-step (chunk pair index)
                uint32_t a[4][4];
#pragma unroll
                for (int mt = 0; mt < 4; mt++) {
                    int rloc = 64 * wr + 16 * mt + (lane & 15);
                    int ch = 2 * sg + (lane >> 4);
                    uint32_t ad = Abase + rloc * 256 + ((ch ^ (rloc & 7)) << 4);
                    ldsm_x4(ad, a[mt][0], a[mt][1], a[mt][2], a[mt][3]);
                }
                uint32_t b[4][2];
#pragma unroll
                for (int p = 0; p < 2; p++) {
                    int nloc = 32 * wc + 16 * p + (lane & 7) + ((lane >> 4) << 3);
                    int ch = 2 * s2 + ((lane >> 3) & 1);
                    uint32_t ad = Bbase + nloc * 128 + ((ch ^ (nloc & 7)) << 4);
                    ldsm_x4(ad, b[2 * p][0], b[2 * p][1], b[2 * p + 1][0], b[2 * p + 1][1]);
                }
#pragma unroll
                for (int mt = 0; mt < 4; mt++)
#pragma unroll
                    for (int nt = 0; nt < 4; nt++)
                        mma16816(acc[mt][nt], a[mt], b[nt]);
            }
        }

        // Epilogue: mask diag, exp-accumulate, capture positives
#pragma unroll
        for (int mt = 0; mt < 4; mt++)
#pragma unroll
            for (int e = 0; e < 4; e++) {
                int row = i0 + 64 * wr + 16 * mt + (lane >> 2) + 8 * (e >> 1);
                int pj = (row + B_) & (N_ - 1);
                float racc = 0.0f;
#pragma unroll
                for (int nt = 0; nt < 4; nt++) {
                    int col = j0 + 32 * wc + 8 * nt + 2 * (lane & 3) + (e & 1);
                    float s = 2.0f * acc[mt][nt][e];   // / temperature
                    if (col != row) racc += __expf(s);
                    if (col == pj) g_pos[row] = s;
                }
                rowacc[mt * 2 + (e >> 1)] += racc;
            }
    }

    // Reduce across the 4 lanes (lane&3) sharing the same rows, then store.
#pragma unroll
    for (int idx = 0; idx < 8; idx++) {
        float v = rowacc[idx];
        v += __shfl_xor_sync(0xffffffffu, v, 1);
        v += __shfl_xor_sync(0xffffffffu, v, 2);
        if ((lane & 3) == 0) {
            int row = i0 + 64 * wr + 16 * (idx >> 1) + (lane >> 2) + 8 * (idx & 1);
            g_rowsum_part[(blockIdx.y * 4 + wc) * N_ + row] = v;
        }
    }
}

// ---------------------------------------------------------------------------
// Kernel 3: loss = mean_i( log(sum of 32 partials) - pos_i )
// ---------------------------------------------------------------------------
__global__ __launch_bounds__(256) void finalize_kernel(float* __restrict__ out)
{
    __shared__ double red[256];
    const int tid = threadIdx.x;
    double acc = 0.0;
    for (int i = tid; i < N_; i += 256) {
        float rs = 0.0f;
#pragma unroll
        for (int p = 0; p < 32; p++) rs += g_rowsum_part[p * N_ + i];
        acc += (double)logf(rs) - (double)g_pos[i];
    }
    red[tid] = acc;
    __syncthreads();
    for (int s = 128; s > 0; s >>= 1) {
        if (tid < s) red[tid] += red[tid + s];
        __syncthreads();
    }
    if (tid == 0) out[0] = (float)(red[0] / (double)N_);
}

// ---------------------------------------------------------------------------
extern "C" void kernel_launch(void* const* d_in, const int* in_sizes, int n_in,
                              void* d_out, int out_size)
{
    const float* zi = (const float*)d_in[0];
    const float* zj = (const float*)d_in[1];
    const float* W  = (const float*)d_in[2];
    const float* b  = (const float*)d_in[3];
    float* out = (float*)d_out;

    gemm1_norm_kernel<<<128, 256>>>(zi, zj, W, b);
    sim_rowsum_kernel<<<dim3(64, 8), 256>>>();
    finalize_kernel<<<1, 256>>>(out);
}

// round 5
// speedup vs baseline: 6.3816x; 1.0484x over previous
#include <cuda_runtime.h>
#include <cuda_bf16.h>
#include <math.h>
#include <stdint.h>

// Problem constants
#define B_    4096
#define DIN_  2048
#define DOUT_ 128
#define N_    8192   // 2*B_

// Scratch (device globals -- no allocation allowed)
__device__ __nv_bfloat16 g_znb[N_ * DOUT_];    // normalized reps, bf16, 2 MB
__device__ __nv_bfloat16 g_wb[DOUT_ * DIN_];   // W in bf16, 512 KB
__device__ float g_rowsum_part[32 * N_];       // per-(jsplit,warpcol) partials
__device__ float g_pos[N_];                    // positive-pair logits

__device__ __forceinline__ uint32_t sptr(const void* p) {
    return (uint32_t)__cvta_generic_to_shared(p);
}

__device__ __forceinline__ void ldsm_x4(uint32_t addr, uint32_t& r0, uint32_t& r1,
                                        uint32_t& r2, uint32_t& r3) {
    asm volatile("ldmatrix.sync.aligned.m8n8.x4.shared.b16 {%0,%1,%2,%3}, [%4];"
                 : "=r"(r0), "=r"(r1), "=r"(r2), "=r"(r3) : "r"(addr));
}

__device__ __forceinline__ void mma16816(float* c, const uint32_t* a, const uint32_t* b) {
    asm volatile(
        "mma.sync.aligned.m16n8k16.row.col.f32.bf16.bf16.f32 "
        "{%0,%1,%2,%3}, {%4,%5,%6,%7}, {%8,%9}, {%0,%1,%2,%3};"
        : "+f"(c[0]), "+f"(c[1]), "+f"(c[2]), "+f"(c[3])
        : "r"(a[0]), "r"(a[1]), "r"(a[2]), "r"(a[3]), "r"(b[0]), "r"(b[1]));
}

__device__ __forceinline__ void cpa16(uint32_t smem_addr, const void* gptr) {
    asm volatile("cp.async.cg.shared.global.L2::128B [%0], [%1], 16;"
                 :: "r"(smem_addr), "l"(gptr) : "memory");
}

__device__ __forceinline__ void sts16(uint32_t addr, uint4 v) {
    asm volatile("st.shared.v4.b32 [%0], {%1,%2,%3,%4};"
                 :: "r"(addr), "r"(v.x), "r"(v.y), "r"(v.z), "r"(v.w) : "memory");
}

// ---------------------------------------------------------------------------
// Kernel 0: convert W (fp32) -> g_wb (bf16). 128 blocks x 256 thr, 8 elems/thr.
// ---------------------------------------------------------------------------
__global__ __launch_bounds__(256) void wconv_kernel(const float* __restrict__ W)
{
    int idx = blockIdx.x * 256 + threadIdx.x;   // one 8-elem group
    const float4* src = (const float4*)W;
    float4 v0 = src[2 * idx];
    float4 v1 = src[2 * idx + 1];
    __nv_bfloat162 h[4];
    h[0] = __floats2bfloat162_rn(v0.x, v0.y);
    h[1] = __floats2bfloat162_rn(v0.z, v0.w);
    h[2] = __floats2bfloat162_rn(v1.x, v1.y);
    h[3] = __floats2bfloat162_rn(v1.z, v1.w);
    *(uint4*)&g_wb[idx * 8] = *(uint4*)h;
}

// ---------------------------------------------------------------------------
// Kernel 1: H = relu(Z) @ Wb^T + b (bf16 HMMA), pipelined, then normalize.
// 128 blocks x 256 thr. Block tile 64 rows x 128 cols; k-chunks of 128,
// double-buffered: Wb via cp.async, Z via register prefetch + convert.
// Dynamic smem: 1K slack + 2x16KB A stages + 2x32KB W stages.
// ---------------------------------------------------------------------------
#define G1_SMEM_BYTES 99328

__global__ __launch_bounds__(256) void gemm1_norm_kernel(
    const float* __restrict__ zi, const float* __restrict__ zj,
    const float* __restrict__ bias)
{
    extern __shared__ __align__(16) unsigned char dynsm[];
    const uint32_t smraw = sptr(dynsm);
    const uint32_t smbase = (smraw + 1023) & ~1023u;
    const uint32_t As[2] = {smbase, smbase + 16384};
    const uint32_t Ws[2] = {smbase + 32768, smbase + 65536};

    const int tid = threadIdx.x;
    const int lane = tid & 31;
    const int warp = tid >> 5;       // cols 16*warp .. +16
    const int i0 = blockIdx.x * 64;

    const float* Z = (i0 < B_) ? zi : zj;
    const int zr0 = (i0 < B_) ? i0 : (i0 - B_);

    float acc[4][2][4];
#pragma unroll
    for (int mt = 0; mt < 4; mt++)
#pragma unroll
        for (int nt = 0; nt < 2; nt++)
#pragma unroll
            for (int e = 0; e < 4; e++) acc[mt][nt][e] = 0.0f;

    float4 av[8];   // A register prefetch: 4 groups x 8 floats

    // --- helpers (lambdas) ---
    auto fetch_A = [&](int kc) {
#pragma unroll
        for (int it = 0; it < 4; it++) {
            int e = tid + it * 256;
            int r = e >> 4, c = e & 15;
            const float* src = &Z[(size_t)(zr0 + r) * DIN_ + kc * 128 + c * 8];
            av[2 * it]     = *(const float4*)src;
            av[2 * it + 1] = *(const float4*)(src + 4);
        }
    };
    auto store_A = [&](int stg) {
#pragma unroll
        for (int it = 0; it < 4; it++) {
            int e = tid + it * 256;
            int r = e >> 4, c = e & 15;
            float4 v0 = av[2 * it], v1 = av[2 * it + 1];
            __nv_bfloat162 h[4];
            h[0] = __floats2bfloat162_rn(fmaxf(v0.x, 0.f), fmaxf(v0.y, 0.f));
            h[1] = __floats2bfloat162_rn(fmaxf(v0.z, 0.f), fmaxf(v0.w, 0.f));
            h[2] = __floats2bfloat162_rn(fmaxf(v1.x, 0.f), fmaxf(v1.y, 0.f));
            h[3] = __floats2bfloat162_rn(fmaxf(v1.z, 0.f), fmaxf(v1.w, 0.f));
            sts16(As[stg] + r * 256 + ((c ^ (r & 7)) << 4), *(uint4*)h);
        }
    };
    auto load_W = [&](int kc, int stg) {
#pragma unroll
        for (int it = 0; it < 8; it++) {
            int e = tid + it * 256;
            int r = e >> 4, c = e & 15;
            cpa16(Ws[stg] + r * 256 + ((c ^ (r & 7)) << 4),
                  &g_wb[(size_t)r * DIN_ + kc * 128 + c * 8]);
        }
        asm volatile("cp.async.commit_group;" ::: "memory");
    };

    // --- prologue: chunk 0 ---
    fetch_A(0);
    load_W(0, 0);
    store_A(0);

    for (int kc = 0; kc < 16; kc++) {
        const int stg = kc & 1;
        asm volatile("cp.async.wait_group 0;" ::: "memory");
        __syncthreads();   // stage `stg` ready; other stage free for overwrite

        if (kc + 1 < 16) {
            fetch_A(kc + 1);
            load_W(kc + 1, stg ^ 1);
        }

        const uint32_t Abase = As[stg], Wbase = Ws[stg];
#pragma unroll
        for (int s = 0; s < 8; s++) {
            uint32_t a[4][4];
#pragma unroll
            for (int mt = 0; mt < 4; mt++) {
                int rloc = 16 * mt + (lane & 15);
                int ch = 2 * s + (lane >> 4);
                uint32_t ad = Abase + rloc * 256 + ((ch ^ (rloc & 7)) << 4);
                ldsm_x4(ad, a[mt][0], a[mt][1], a[mt][2], a[mt][3]);
            }
            uint32_t b[2][2];
            {
                int nloc = 16 * warp + (lane & 7) + ((lane >> 4) << 3);
                int ch = 2 * s + ((lane >> 3) & 1);
                uint32_t ad = Wbase + nloc * 256 + ((ch ^ (nloc & 7)) << 4);
                ldsm_x4(ad, b[0][0], b[0][1], b[1][0], b[1][1]);
            }
#pragma unroll
            for (int mt = 0; mt < 4; mt++)
#pragma unroll
                for (int nt = 0; nt < 2; nt++)
                    mma16816(acc[mt][nt], a[mt], b[nt]);
        }

        if (kc + 1 < 16) store_A(stg ^ 1);
    }

    // Epilogue: stage h = acc + bias into smem, then normalize rows.
    __syncthreads();
    float* hsm = (float*)dynsm;  // [64][132]
    {
        float bcol[2][2];
#pragma unroll
        for (int nt = 0; nt < 2; nt++)
#pragma unroll
            for (int e2 = 0; e2 < 2; e2++)
                bcol[nt][e2] = __ldg(&bias[16 * warp + 8 * nt + 2 * (lane & 3) + e2]);
#pragma unroll
        for (int mt = 0; mt < 4; mt++)
#pragma unroll
            for (int nt = 0; nt < 2; nt++)
#pragma unroll
                for (int e = 0; e < 4; e++) {
                    int row = 16 * mt + (lane >> 2) + 8 * (e >> 1);
                    int col = 16 * warp + 8 * nt + 2 * (lane & 3) + (e & 1);
                    hsm[row * 132 + col] = acc[mt][nt][e] + bcol[nt][e & 1];
                }
    }
    __syncthreads();

#pragma unroll
    for (int rr = 0; rr < 8; rr++) {
        int r = 8 * warp + rr;
        float v[4], ss = 0.0f;
#pragma unroll
        for (int q = 0; q < 4; q++) {
            v[q] = hsm[r * 132 + lane + 32 * q];
            ss += v[q] * v[q];
        }
#pragma unroll
        for (int m = 16; m > 0; m >>= 1)
            ss += __shfl_xor_sync(0xffffffffu, ss, m);
        float inv = 1.0f / fmaxf(sqrtf(ss), 1e-8f);
        int gi = i0 + r;
#pragma unroll
        for (int q = 0; q < 4; q++)
            g_znb[(size_t)gi * DOUT_ + lane + 32 * q] = __float2bfloat16(v[q] * inv);
    }
}

// ---------------------------------------------------------------------------
// Kernel 2 (R1, known-good): sim rowsums via bf16 mma.sync.
// Grid (64, 8): 128-row i-tile x 1024-col j-split. 8 warps as 2x4.
// ---------------------------------------------------------------------------
__global__ __launch_bounds__(256, 2) void sim_rowsum_kernel()
{
    __shared__ __align__(16) unsigned char smraw[49152];
    unsigned char* Asm = smraw;           // [128][256B] swizzled
    unsigned char* Bsm = smraw + 32768;   // [128][128B] swizzled
    const uint32_t Abase = sptr(Asm);
    const uint32_t Bbase = sptr(Bsm);

    const int tid = threadIdx.x;
    const int lane = tid & 31;
    const int warp = tid >> 5;
    const int wr = warp >> 2;
    const int wc = warp & 3;
    const int i0 = blockIdx.x * 128;
    const int jbase = blockIdx.y * 1024;

#pragma unroll
    for (int it = 0; it < 8; it++) {
        int e = tid + it * 256;
        int r = e >> 4, c = e & 15;
        uint4 v = *(const uint4*)&g_znb[(size_t)(i0 + r) * DOUT_ + c * 8];
        int cs = c ^ (r & 7);
        *(uint4*)(Asm + r * 256 + cs * 16) = v;
    }

    float rowacc[8];
#pragma unroll
    for (int x = 0; x < 8; x++) rowacc[x] = 0.0f;

    for (int jt = 0; jt < 8; jt++) {
        const int j0 = jbase + jt * 128;

        float acc[4][4][4];
#pragma unroll
        for (int mt = 0; mt < 4; mt++)
#pragma unroll
            for (int nt = 0; nt < 4; nt++)
#pragma unroll
                for (int e = 0; e < 4; e++) acc[mt][nt][e] = 0.0f;

#pragma unroll
        for (int kc = 0; kc < 2; kc++) {
            __syncthreads();
#pragma unroll
            for (int it = 0; it < 4; it++) {
                int e = tid + it * 256;
                int r = e >> 3, c = e & 7;
                uint4 v = *(const uint4*)&g_znb[(size_t)(j0 + r) * DOUT_ + kc * 64 + c * 8];
                int cs = c ^ (r & 7);
                *(uint4*)(Bsm + r * 128 + cs * 16) = v;
            }
            __syncthreads();

#pragma unroll
            for (int s2 = 0; s2 < 4; s2++) {
                int sg = kc * 4 + s2;
                uint32_t a[4][4];
#pragma unroll
                for (int mt = 0; mt < 4; mt++) {
                    int rloc = 64 * wr + 16 * mt + (lane & 15);
                    int ch = 2 * sg + (lane >> 4);
                    uint32_t ad = Abase + rloc * 256 + ((ch ^ (rloc & 7)) << 4);
                    ldsm_x4(ad, a[mt][0], a[mt][1], a[mt][2], a[mt][3]);
                }
                uint32_t b[4][2];
#pragma unroll
                for (int p = 0; p < 2; p++) {
                    int nloc = 32 * wc + 16 * p + (lane & 7) + ((lane >> 4) << 3);
                    int ch = 2 * s2 + ((lane >> 3) & 1);
                    uint32_t ad = Bbase + nloc * 128 + ((ch ^ (nloc & 7)) << 4);
                    ldsm_x4(ad, b[2 * p][0], b[2 * p][1], b[2 * p + 1][0], b[2 * p + 1][1]);
                }
#pragma unroll
                for (int mt = 0; mt < 4; mt++)
#pragma unroll
                    for (int nt = 0; nt < 4; nt++)
                        mma16816(acc[mt][nt], a[mt], b[nt]);
            }
        }

#pragma unroll
        for (int mt = 0; mt < 4; mt++)
#pragma unroll
            for (int e = 0; e < 4; e++) {
                int row = i0 + 64 * wr + 16 * mt + (lane >> 2) + 8 * (e >> 1);
                int pj = (row + B_) & (N_ - 1);
                float racc = 0.0f;
#pragma unroll
                for (int nt = 0; nt < 4; nt++) {
                    int col = j0 + 32 * wc + 8 * nt + 2 * (lane & 3) + (e & 1);
                    float s = 2.0f * acc[mt][nt][e];   // / temperature
                    if (col != row) racc += __expf(s);
                    if (col == pj) g_pos[row] = s;
                }
                rowacc[mt * 2 + (e >> 1)] += racc;
            }
    }

#pragma unroll
    for (int idx = 0; idx < 8; idx++) {
        float v = rowacc[idx];
        v += __shfl_xor_sync(0xffffffffu, v, 1);
        v += __shfl_xor_sync(0xffffffffu, v, 2);
        if ((lane & 3) == 0) {
            int row = i0 + 64 * wr + 16 * (idx >> 1) + (lane >> 2) + 8 * (idx & 1);
            g_rowsum_part[(blockIdx.y * 4 + wc) * N_ + row] = v;
        }
    }
}

// ---------------------------------------------------------------------------
// Kernel 3: loss = mean_i( log(sum of 32 partials) - pos_i )
// ---------------------------------------------------------------------------
__global__ __launch_bounds__(256) void finalize_kernel(float* __restrict__ out)
{
    __shared__ double red[256];
    const int tid = threadIdx.x;
    double acc = 0.0;
    for (int i = tid; i < N_; i += 256) {
        float rs = 0.0f;
#pragma unroll
        for (int p = 0; p < 32; p++) rs += g_rowsum_part[p * N_ + i];
        acc += (double)logf(rs) - (double)g_pos[i];
    }
    red[tid] = acc;
    __syncthreads();
    for (int s = 128; s > 0; s >>= 1) {
        if (tid < s) red[tid] += red[tid + s];
        __syncthreads();
    }
    if (tid == 0) out[0] = (float)(red[0] / (double)N_);
}

// ---------------------------------------------------------------------------
extern "C" void kernel_launch(void* const* d_in, const int* in_sizes, int n_in,
                              void* d_out, int out_size)
{
    const float* zi = (const float*)d_in[0];
    const float* zj = (const float*)d_in[1];
    const float* W  = (const float*)d_in[2];
    const float* b  = (const float*)d_in[3];
    float* out = (float*)d_out;

    static int attr_done = 0;
    if (!attr_done) {
        cudaFuncSetAttribute(gemm1_norm_kernel,
                             cudaFuncAttributeMaxDynamicSharedMemorySize,
                             G1_SMEM_BYTES);
        attr_done = 1;
    }

    wconv_kernel<<<128, 256>>>(W);
    gemm1_norm_kernel<<<128, 256, G1_SMEM_BYTES>>>(zi, zj, b);
    sim_rowsum_kernel<<<dim3(64, 8), 256>>>();
    finalize_kernel<<<1, 256>>>(out);
}

// round 9
// speedup vs baseline: 8.3490x; 1.3083x over previous
#include <cuda_runtime.h>
#include <cuda_bf16.h>
#include <math.h>
#include <stdint.h>

// Problem constants
#define B_    4096
#define DIN_  2048
#define DOUT_ 128
#define N_    8192   // 2*B_

// Scratch (device globals -- no allocation allowed)
__device__ __nv_bfloat16 g_znb[N_ * DOUT_];    // normalized reps, bf16, 2 MB
__device__ __nv_bfloat16 g_wb[DOUT_ * DIN_];   // W in bf16, 512 KB
__device__ float g_h0[N_ * DOUT_];             // split-K partial 0, fp32, 4 MB
__device__ float g_h1[N_ * DOUT_];             // split-K partial 1, fp32, 4 MB
__device__ float g_rowsum_part[32 * N_];       // per-(jsplit,warpcol) partials
__device__ float g_pos[N_];                    // positive-pair logits
__device__ double g_loss_part[64];             // per-CTA partial losses

__device__ __forceinline__ uint32_t sptr(const void* p) {
    return (uint32_t)__cvta_generic_to_shared(p);
}

__device__ __forceinline__ void ldsm_x4(uint32_t addr, uint32_t& r0, uint32_t& r1,
                                        uint32_t& r2, uint32_t& r3) {
    asm volatile("ldmatrix.sync.aligned.m8n8.x4.shared.b16 {%0,%1,%2,%3}, [%4];"
                 : "=r"(r0), "=r"(r1), "=r"(r2), "=r"(r3) : "r"(addr));
}

__device__ __forceinline__ void mma16816(float* c, const uint32_t* a, const uint32_t* b) {
    asm volatile(
        "mma.sync.aligned.m16n8k16.row.col.f32.bf16.bf16.f32 "
        "{%0,%1,%2,%3}, {%4,%5,%6,%7}, {%8,%9}, {%0,%1,%2,%3};"
        : "+f"(c[0]), "+f"(c[1]), "+f"(c[2]), "+f"(c[3])
        : "r"(a[0]), "r"(a[1]), "r"(a[2]), "r"(a[3]), "r"(b[0]), "r"(b[1]));
}

__device__ __forceinline__ void cpa16(uint32_t smem_addr, const void* gptr) {
    asm volatile("cp.async.cg.shared.global.L2::128B [%0], [%1], 16;"
                 :: "r"(smem_addr), "l"(gptr) : "memory");
}

__device__ __forceinline__ void sts16(uint32_t addr, uint4 v) {
    asm volatile("st.shared.v4.b32 [%0], {%1,%2,%3,%4};"
                 :: "r"(addr), "r"(v.x), "r"(v.y), "r"(v.z), "r"(v.w) : "memory");
}

// ---------------------------------------------------------------------------
// Kernel 0: convert W (fp32) -> g_wb (bf16). 128 blocks x 256 thr, 8 elems/thr.
// ---------------------------------------------------------------------------
__global__ __launch_bounds__(256) void wconv_kernel(const float* __restrict__ W)
{
    int idx = blockIdx.x * 256 + threadIdx.x;   // one 8-elem group
    const float4* src = (const float4*)W;
    float4 v0 = src[2 * idx];
    float4 v1 = src[2 * idx + 1];
    __nv_bfloat162 h[4];
    h[0] = __floats2bfloat162_rn(v0.x, v0.y);
    h[1] = __floats2bfloat162_rn(v0.z, v0.w);
    h[2] = __floats2bfloat162_rn(v1.x, v1.y);
    h[3] = __floats2bfloat162_rn(v1.z, v1.w);
    *(uint4*)&g_wb[idx * 8] = *(uint4*)h;
}

// ---------------------------------------------------------------------------
// Kernel 1: split-K=2 partial GEMM: Hpart = relu(Z) @ Wb[:, khalf]^T.
// Grid 256: tile = blockIdx.x & 127 (64 rows), khalf = blockIdx.x >> 7
// (K range khalf*1024 .. +1024, 8 chunks of 128). 2 CTAs resident per SM.
// No bias / no normalize here -- raw fp32 partials to g_h0/g_h1.
// ---------------------------------------------------------------------------
#define G1_SMEM_BYTES 99328

__global__ __launch_bounds__(256, 2) void gemm1_part_kernel(
    const float* __restrict__ zi, const float* __restrict__ zj)
{
    extern __shared__ __align__(16) unsigned char dynsm[];
    const uint32_t smraw = sptr(dynsm);
    const uint32_t smbase = (smraw + 1023) & ~1023u;
    const uint32_t As[2] = {smbase, smbase + 16384};
    const uint32_t Ws[2] = {smbase + 32768, smbase + 65536};

    const int tid = threadIdx.x;
    const int lane = tid & 31;
    const int warp = tid >> 5;       // cols 16*warp .. +16
    const int tile = blockIdx.x & 127;
    const int khalf = blockIdx.x >> 7;
    const int kbase = khalf * 8;     // chunk offset (chunks of 128)
    const int i0 = tile * 64;

    const float* Z = (i0 < B_) ? zi : zj;
    const int zr0 = (i0 < B_) ? i0 : (i0 - B_);

    float acc[4][2][4];
#pragma unroll
    for (int mt = 0; mt < 4; mt++)
#pragma unroll
        for (int nt = 0; nt < 2; nt++)
#pragma unroll
            for (int e = 0; e < 4; e++) acc[mt][nt][e] = 0.0f;

    float4 av[8];   // A register prefetch: 4 groups x 8 floats

    auto fetch_A = [&](int kc) {
#pragma unroll
        for (int it = 0; it < 4; it++) {
            int e = tid + it * 256;
            int r = e >> 4, c = e & 15;
            const float* src = &Z[(size_t)(zr0 + r) * DIN_ + kc * 128 + c * 8];
            av[2 * it]     = *(const float4*)src;
            av[2 * it + 1] = *(const float4*)(src + 4);
        }
    };
    auto store_A = [&](int stg) {
#pragma unroll
        for (int it = 0; it < 4; it++) {
            int e = tid + it * 256;
            int r = e >> 4, c = e & 15;
            float4 v0 = av[2 * it], v1 = av[2 * it + 1];
            __nv_bfloat162 h[4];
            h[0] = __floats2bfloat162_rn(fmaxf(v0.x, 0.f), fmaxf(v0.y, 0.f));
            h[1] = __floats2bfloat162_rn(fmaxf(v0.z, 0.f), fmaxf(v0.w, 0.f));
            h[2] = __floats2bfloat162_rn(fmaxf(v1.x, 0.f), fmaxf(v1.y, 0.f));
            h[3] = __floats2bfloat162_rn(fmaxf(v1.z, 0.f), fmaxf(v1.w, 0.f));
            sts16(As[stg] + r * 256 + ((c ^ (r & 7)) << 4), *(uint4*)h);
        }
    };
    auto load_W = [&](int kc, int stg) {
#pragma unroll
        for (int it = 0; it < 8; it++) {
            int e = tid + it * 256;
            int r = e >> 4, c = e & 15;
            cpa16(Ws[stg] + r * 256 + ((c ^ (r & 7)) << 4),
                  &g_wb[(size_t)r * DIN_ + kc * 128 + c * 8]);
        }
        asm volatile("cp.async.commit_group;" ::: "memory");
    };

    fetch_A(kbase);
    load_W(kbase, 0);
    store_A(0);

    for (int kc2 = 0; kc2 < 8; kc2++) {
        const int stg = kc2 & 1;
        asm volatile("cp.async.wait_group 0;" ::: "memory");
        __syncthreads();

        if (kc2 + 1 < 8) {
            fetch_A(kbase + kc2 + 1);
            load_W(kbase + kc2 + 1, stg ^ 1);
        }

        const uint32_t Abase = As[stg], Wbase = Ws[stg];
#pragma unroll
        for (int s = 0; s < 8; s++) {
            uint32_t a[4][4];
#pragma unroll
            for (int mt = 0; mt < 4; mt++) {
                int rloc = 16 * mt + (lane & 15);
                int ch = 2 * s + (lane >> 4);
                uint32_t ad = Abase + rloc * 256 + ((ch ^ (rloc & 7)) << 4);
                ldsm_x4(ad, a[mt][0], a[mt][1], a[mt][2], a[mt][3]);
            }
            uint32_t b[2][2];
            {
                int nloc = 16 * warp + (lane & 7) + ((lane >> 4) << 3);
                int ch = 2 * s + ((lane >> 3) & 1);
                uint32_t ad = Wbase + nloc * 256 + ((ch ^ (nloc & 7)) << 4);
                ldsm_x4(ad, b[0][0], b[0][1], b[1][0], b[1][1]);
            }
#pragma unroll
            for (int mt = 0; mt < 4; mt++)
#pragma unroll
                for (int nt = 0; nt < 2; nt++)
                    mma16816(acc[mt][nt], a[mt], b[nt]);
        }

        if (kc2 + 1 < 8) store_A(stg ^ 1);
    }

    // Epilogue: dump raw partials to global (float2 pairs, no smem, no sync).
    float* Hp = khalf ? g_h1 : g_h0;
#pragma unroll
    for (int mt = 0; mt < 4; mt++)
#pragma unroll
        for (int nt = 0; nt < 2; nt++) {
            int r0 = i0 + 16 * mt + (lane >> 2);
            int c0 = 16 * warp + 8 * nt + 2 * (lane & 3);
            *(float2*)&Hp[(size_t)r0 * DOUT_ + c0] =
                make_float2(acc[mt][nt][0], acc[mt][nt][1]);
            *(float2*)&Hp[(size_t)(r0 + 8) * DOUT_ + c0] =
                make_float2(acc[mt][nt][2], acc[mt][nt][3]);
        }
}

// ---------------------------------------------------------------------------
// Kernel 1b: combine partials + bias, row-normalize -> g_znb (bf16).
// 1024 CTAs x 256 thr; one warp per row; fully coalesced.
// ---------------------------------------------------------------------------
__global__ __launch_bounds__(256) void hnorm_kernel(const float* __restrict__ bias)
{
    const int lane = threadIdx.x & 31;
    const int warp = threadIdx.x >> 5;
    const int row = blockIdx.x * 8 + warp;

    float hx[4];
    float ss = 0.0f;
#pragma unroll
    for (int q = 0; q < 2; q++) {
        int c = 2 * lane + 64 * q;
        float2 a = *(const float2*)&g_h0[(size_t)row * DOUT_ + c];
        float2 b = *(const float2*)&g_h1[(size_t)row * DOUT_ + c];
        float2 bb = *(const float2*)&bias[c];
        float x = a.x + b.x + bb.x;
        float y = a.y + b.y + bb.y;
        hx[2 * q] = x; hx[2 * q + 1] = y;
        ss += x * x + y * y;
    }
#pragma unroll
    for (int m = 16; m > 0; m >>= 1)
        ss += __shfl_xor_sync(0xffffffffu, ss, m);
    float inv = 1.0f / fmaxf(sqrtf(ss), 1e-8f);
#pragma unroll
    for (int q = 0; q < 2; q++) {
        int c = 2 * lane + 64 * q;
        *(__nv_bfloat162*)&g_znb[(size_t)row * DOUT_ + c] =
            __floats2bfloat162_rn(hx[2 * q] * inv, hx[2 * q + 1] * inv);
    }
}

// ---------------------------------------------------------------------------
// Kernel 2: sim rowsums via bf16 mma.sync. Grid (64, 8), 8 warps as 2x4.
// ---------------------------------------------------------------------------
__global__ __launch_bounds__(256, 2) void sim_rowsum_kernel()
{
    __shared__ __align__(16) unsigned char smraw[49152];
    unsigned char* Asm = smraw;           // [128][256B] swizzled
    unsigned char* Bsm = smraw + 32768;   // [128][128B] swizzled
    const uint32_t Abase = sptr(Asm);
    const uint32_t Bbase = sptr(Bsm);

    const int tid = threadIdx.x;
    const int lane = tid & 31;
    const int warp = tid >> 5;
    const int wr = warp >> 2;
    const int wc = warp & 3;
    const int i0 = blockIdx.x * 128;
    const int jbase = blockIdx.y * 1024;

#pragma unroll
    for (int it = 0; it < 8; it++) {
        int e = tid + it * 256;
        int r = e >> 4, c = e & 15;
        uint4 v = *(const uint4*)&g_znb[(size_t)(i0 + r) * DOUT_ + c * 8];
        int cs = c ^ (r & 7);
        *(uint4*)(Asm + r * 256 + cs * 16) = v;
    }

    float rowacc[8];
#pragma unroll
    for (int x = 0; x < 8; x++) rowacc[x] = 0.0f;

    for (int jt = 0; jt < 8; jt++) {
        const int j0 = jbase + jt * 128;

        float acc[4][4][4];
#pragma unroll
        for (int mt = 0; mt < 4; mt++)
#pragma unroll
            for (int nt = 0; nt < 4; nt++)
#pragma unroll
                for (int e = 0; e < 4; e++) acc[mt][nt][e] = 0.0f;

#pragma unroll
        for (int kc = 0; kc < 2; kc++) {
            __syncthreads();
#pragma unroll
            for (int it = 0; it < 4; it++) {
                int e = tid + it * 256;
                int r = e >> 3, c = e & 7;
                uint4 v = *(const uint4*)&g_znb[(size_t)(j0 + r) * DOUT_ + kc * 64 + c * 8];
                int cs = c ^ (r & 7);
                *(uint4*)(Bsm + r * 128 + cs * 16) = v;
            }
            __syncthreads();

#pragma unroll
            for (int s2 = 0; s2 < 4; s2++) {
                int sg = kc * 4 + s2;
                uint32_t a[4][4];
#pragma unroll
                for (int mt = 0; mt < 4; mt++) {
                    int rloc = 64 * wr + 16 * mt + (lane & 15);
                    int ch = 2 * sg + (lane >> 4);
                    uint32_t ad = Abase + rloc * 256 + ((ch ^ (rloc & 7)) << 4);
                    ldsm_x4(ad, a[mt][0], a[mt][1], a[mt][2], a[mt][3]);
                }
                uint32_t b[4][2];
#pragma unroll
                for (int p = 0; p < 2; p++) {
                    int nloc = 32 * wc + 16 * p + (lane & 7) + ((lane >> 4) << 3);
                    int ch = 2 * s2 + ((lane >> 3) & 1);
                    uint32_t ad = Bbase + nloc * 128 + ((ch ^ (nloc & 7)) << 4);
                    ldsm_x4(ad, b[2 * p][0], b[2 * p][1], b[2 * p + 1][0], b[2 * p + 1][1]);
                }
#pragma unroll
                for (int mt = 0; mt < 4; mt++)
#pragma unroll
                    for (int nt = 0; nt < 4; nt++)
                        mma16816(acc[mt][nt], a[mt], b[nt]);
            }
        }

#pragma unroll
        for (int mt = 0; mt < 4; mt++)
#pragma unroll
            for (int e = 0; e < 4; e++) {
                int row = i0 + 64 * wr + 16 * mt + (lane >> 2) + 8 * (e >> 1);
                int pj = (row + B_) & (N_ - 1);
                float racc = 0.0f;
#pragma unroll
                for (int nt = 0; nt < 4; nt++) {
                    int col = j0 + 32 * wc + 8 * nt + 2 * (lane & 3) + (e & 1);
                    float s = 2.0f * acc[mt][nt][e];   // / temperature
                    if (col != row) racc += __expf(s);
                    if (col == pj) g_pos[row] = s;
                }
                rowacc[mt * 2 + (e >> 1)] += racc;
            }
    }

#pragma unroll
    for (int idx = 0; idx < 8; idx++) {
        float v = rowacc[idx];
        v += __shfl_xor_sync(0xffffffffu, v, 1);
        v += __shfl_xor_sync(0xffffffffu, v, 2);
        if ((lane & 3) == 0) {
            int row = i0 + 64 * wr + 16 * (idx >> 1) + (lane >> 2) + 8 * (idx & 1);
            g_rowsum_part[(blockIdx.y * 4 + wc) * N_ + row] = v;
        }
    }
}

// ---------------------------------------------------------------------------
// Kernel 3a: per-CTA partial loss. 64 CTAs x 256 thr, 128 rows each.
// ---------------------------------------------------------------------------
__global__ __launch_bounds__(256) void finalize_part_kernel()
{
    __shared__ double red[256];
    const int tid = threadIdx.x;
    const int base = blockIdx.x * 128;
    double acc = 0.0;
    {
        int row = base + (tid & 127);
        int half = tid >> 7;           // 0 or 1
        float rs = 0.0f;
#pragma unroll
        for (int p = 0; p < 16; p++)
            rs += g_rowsum_part[(16 * half + p) * N_ + row];
        red[tid] = (double)rs;
    }
    __syncthreads();
    if (tid < 128) {
        int row = base + tid;
        float rs = (float)(red[tid] + red[tid + 128]);
        acc = (double)logf(rs) - (double)g_pos[row];
    }
    __syncthreads();
    red[tid] = (tid < 128) ? acc : 0.0;
    __syncthreads();
    for (int s = 128; s > 0; s >>= 1) {
        if (tid < s) red[tid] += red[tid + s];
        __syncthreads();
    }
    if (tid == 0) g_loss_part[blockIdx.x] = red[0];
}

// ---------------------------------------------------------------------------
// Kernel 3b: sum 64 partials -> loss.
// ---------------------------------------------------------------------------
__global__ __launch_bounds__(64) void finalize_final_kernel(float* __restrict__ out)
{
    const int tid = threadIdx.x;
    double v = g_loss_part[tid];
#pragma unroll
    for (int m = 16; m > 0; m >>= 1)
        v += __shfl_xor_sync(0xffffffffu, v, m);
    __shared__ double wsum[2];
    if ((tid & 31) == 0) wsum[tid >> 5] = v;
    __syncthreads();
    if (tid == 0) out[0] = (float)((wsum[0] + wsum[1]) / (double)N_);
}

// ---------------------------------------------------------------------------
extern "C" void kernel_launch(void* const* d_in, const int* in_sizes, int n_in,
                              void* d_out, int out_size)
{
    const float* zi = (const float*)d_in[0];
    const float* zj = (const float*)d_in[1];
    const float* W  = (const float*)d_in[2];
    const float* b  = (const float*)d_in[3];
    float* out = (float*)d_out;

    static int attr_done = 0;
    if (!attr_done) {
        cudaFuncSetAttribute(gemm1_part_kernel,
                             cudaFuncAttributeMaxDynamicSharedMemorySize,
                             G1_SMEM_BYTES);
        attr_done = 1;
    }

    wconv_kernel<<<128, 256>>>(W);
    gemm1_part_kernel<<<256, 256, G1_SMEM_BYTES>>>(zi, zj);
    hnorm_kernel<<<1024, 256>>>(b);
    sim_rowsum_kernel<<<dim3(64, 8), 256>>>();
    finalize_part_kernel<<<64, 256>>>();
    finalize_final_kernel<<<1, 64>>>(out);
}

// round 12
// speedup vs baseline: 8.4079x; 1.0070x over previous
#include <cuda_runtime.h>
#include <cuda_bf16.h>
#include <math.h>
#include <stdint.h>

// Problem constants
#define B_    4096
#define DIN_  2048
#define DOUT_ 128
#define N_    8192   // 2*B_

// Scratch (device globals -- no allocation allowed)
__device__ __nv_bfloat16 g_znb[N_ * DOUT_];    // normalized reps, bf16, 2 MB
__device__ __nv_bfloat16 g_wb[DOUT_ * DIN_];   // W in bf16, 512 KB
__device__ float g_h0[N_ * DOUT_];             // split-K partial 0, fp32, 4 MB
__device__ float g_h1[N_ * DOUT_];             // split-K partial 1, fp32, 4 MB
__device__ float g_rowsum_part[32 * N_];       // per-(jsplit,warpcol) partials
__device__ float g_pos[N_];                    // positive-pair logits
__device__ double g_loss_part[64];             // per-CTA partial losses

__device__ __forceinline__ uint32_t sptr(const void* p) {
    return (uint32_t)__cvta_generic_to_shared(p);
}

__device__ __forceinline__ void ldsm_x4(uint32_t addr, uint32_t& r0, uint32_t& r1,
                                        uint32_t& r2, uint32_t& r3) {
    asm volatile("ldmatrix.sync.aligned.m8n8.x4.shared.b16 {%0,%1,%2,%3}, [%4];"
                 : "=r"(r0), "=r"(r1), "=r"(r2), "=r"(r3) : "r"(addr));
}

__device__ __forceinline__ void mma16816(float* c, const uint32_t* a, const uint32_t* b) {
    asm volatile(
        "mma.sync.aligned.m16n8k16.row.col.f32.bf16.bf16.f32 "
        "{%0,%1,%2,%3}, {%4,%5,%6,%7}, {%8,%9}, {%0,%1,%2,%3};"
        : "+f"(c[0]), "+f"(c[1]), "+f"(c[2]), "+f"(c[3])
        : "r"(a[0]), "r"(a[1]), "r"(a[2]), "r"(a[3]), "r"(b[0]), "r"(b[1]));
}

__device__ __forceinline__ void cpa16(uint32_t smem_addr, const void* gptr) {
    asm volatile("cp.async.cg.shared.global.L2::128B [%0], [%1], 16;"
                 :: "r"(smem_addr), "l"(gptr) : "memory");
}

__device__ __forceinline__ void sts16(uint32_t addr, uint4 v) {
    asm volatile("st.shared.v4.b32 [%0], {%1,%2,%3,%4};"
                 :: "r"(addr), "r"(v.x), "r"(v.y), "r"(v.z), "r"(v.w) : "memory");
}

// ---------------------------------------------------------------------------
// Kernel 0: convert W (fp32) -> g_wb (bf16). 128 blocks x 256 thr, 8 elems/thr.
// ---------------------------------------------------------------------------
__global__ __launch_bounds__(256) void wconv_kernel(const float* __restrict__ W)
{
    int idx = blockIdx.x * 256 + threadIdx.x;   // one 8-elem group
    const float4* src = (const float4*)W;
    float4 v0 = src[2 * idx];
    float4 v1 = src[2 * idx + 1];
    __nv_bfloat162 h[4];
    h[0] = __floats2bfloat162_rn(v0.x, v0.y);
    h[1] = __floats2bfloat162_rn(v0.z, v0.w);
    h[2] = __floats2bfloat162_rn(v1.x, v1.y);
    h[3] = __floats2bfloat162_rn(v1.z, v1.w);
    *(uint4*)&g_wb[idx * 8] = *(uint4*)h;
}

// ---------------------------------------------------------------------------
// Kernel 1: split-K=2 partial GEMM: Hpart = relu(Z) @ Wb[:, khalf]^T.
// ---------------------------------------------------------------------------
#define G1_SMEM_BYTES 99328

__global__ __launch_bounds__(256, 2) void gemm1_part_kernel(
    const float* __restrict__ zi, const float* __restrict__ zj)
{
    extern __shared__ __align__(16) unsigned char dynsm[];
    const uint32_t smraw = sptr(dynsm);
    const uint32_t smbase = (smraw + 1023) & ~1023u;
    const uint32_t As[2] = {smbase, smbase + 16384};
    const uint32_t Ws[2] = {smbase + 32768, smbase + 65536};

    const int tid = threadIdx.x;
    const int lane = tid & 31;
    const int warp = tid >> 5;       // cols 16*warp .. +16
    const int tile = blockIdx.x & 127;
    const int khalf = blockIdx.x >> 7;
    const int kbase = khalf * 8;     // chunk offset (chunks of 128)
    const int i0 = tile * 64;

    const float* Z = (i0 < B_) ? zi : zj;
    const int zr0 = (i0 < B_) ? i0 : (i0 - B_);

    float acc[4][2][4];
#pragma unroll
    for (int mt = 0; mt < 4; mt++)
#pragma unroll
        for (int nt = 0; nt < 2; nt++)
#pragma unroll
            for (int e = 0; e < 4; e++) acc[mt][nt][e] = 0.0f;

    float4 av[8];   // A register prefetch: 4 groups x 8 floats

    auto fetch_A = [&](int kc) {
#pragma unroll
        for (int it = 0; it < 4; it++) {
            int e = tid + it * 256;
            int r = e >> 4, c = e & 15;
            const float* src = &Z[(size_t)(zr0 + r) * DIN_ + kc * 128 + c * 8];
            av[2 * it]     = *(const float4*)src;
            av[2 * it + 1] = *(const float4*)(src + 4);
        }
    };
    auto store_A = [&](int stg) {
#pragma unroll
        for (int it = 0; it < 4; it++) {
            int e = tid + it * 256;
            int r = e >> 4, c = e & 15;
            float4 v0 = av[2 * it], v1 = av[2 * it + 1];
            __nv_bfloat162 h[4];
            h[0] = __floats2bfloat162_rn(fmaxf(v0.x, 0.f), fmaxf(v0.y, 0.f));
            h[1] = __floats2bfloat162_rn(fmaxf(v0.z, 0.f), fmaxf(v0.w, 0.f));
            h[2] = __floats2bfloat162_rn(fmaxf(v1.x, 0.f), fmaxf(v1.y, 0.f));
            h[3] = __floats2bfloat162_rn(fmaxf(v1.z, 0.f), fmaxf(v1.w, 0.f));
            sts16(As[stg] + r * 256 + ((c ^ (r & 7)) << 4), *(uint4*)h);
        }
    };
    auto load_W = [&](int kc, int stg) {
#pragma unroll
        for (int it = 0; it < 8; it++) {
            int e = tid + it * 256;
            int r = e >> 4, c = e & 15;
            cpa16(Ws[stg] + r * 256 + ((c ^ (r & 7)) << 4),
                  &g_wb[(size_t)r * DIN_ + kc * 128 + c * 8]);
        }
        asm volatile("cp.async.commit_group;" ::: "memory");
    };

    fetch_A(kbase);
    load_W(kbase, 0);
    store_A(0);

    for (int kc2 = 0; kc2 < 8; kc2++) {
        const int stg = kc2 & 1;
        asm volatile("cp.async.wait_group 0;" ::: "memory");
        __syncthreads();

        if (kc2 + 1 < 8) {
            fetch_A(kbase + kc2 + 1);
            load_W(kbase + kc2 + 1, stg ^ 1);
        }

        const uint32_t Abase = As[stg], Wbase = Ws[stg];
#pragma unroll
        for (int s = 0; s < 8; s++) {
            uint32_t a[4][4];
#pragma unroll
            for (int mt = 0; mt < 4; mt++) {
                int rloc = 16 * mt + (lane & 15);
                int ch = 2 * s + (lane >> 4);
                uint32_t ad = Abase + rloc * 256 + ((ch ^ (rloc & 7)) << 4);
                ldsm_x4(ad, a[mt][0], a[mt][1], a[mt][2], a[mt][3]);
            }
            uint32_t b[2][2];
            {
                int nloc = 16 * warp + (lane & 7) + ((lane >> 4) << 3);
                int ch = 2 * s + ((lane >> 3) & 1);
                uint32_t ad = Wbase + nloc * 256 + ((ch ^ (nloc & 7)) << 4);
                ldsm_x4(ad, b[0][0], b[0][1], b[1][0], b[1][1]);
            }
#pragma unroll
            for (int mt = 0; mt < 4; mt++)
#pragma unroll
                for (int nt = 0; nt < 2; nt++)
                    mma16816(acc[mt][nt], a[mt], b[nt]);
        }

        if (kc2 + 1 < 8) store_A(stg ^ 1);
    }

    // Epilogue: dump raw partials to global (float2 pairs, no smem, no sync).
    float* Hp = khalf ? g_h1 : g_h0;
#pragma unroll
    for (int mt = 0; mt < 4; mt++)
#pragma unroll
        for (int nt = 0; nt < 2; nt++) {
            int r0 = i0 + 16 * mt + (lane >> 2);
            int c0 = 16 * warp + 8 * nt + 2 * (lane & 3);
            *(float2*)&Hp[(size_t)r0 * DOUT_ + c0] =
                make_float2(acc[mt][nt][0], acc[mt][nt][1]);
            *(float2*)&Hp[(size_t)(r0 + 8) * DOUT_ + c0] =
                make_float2(acc[mt][nt][2], acc[mt][nt][3]);
        }
}

// ---------------------------------------------------------------------------
// Kernel 1b: combine partials + bias, row-normalize -> g_znb (bf16).
// ---------------------------------------------------------------------------
__global__ __launch_bounds__(256) void hnorm_kernel(const float* __restrict__ bias)
{
    const int lane = threadIdx.x & 31;
    const int warp = threadIdx.x >> 5;
    const int row = blockIdx.x * 8 + warp;

    float hx[4];
    float ss = 0.0f;
#pragma unroll
    for (int q = 0; q < 2; q++) {
        int c = 2 * lane + 64 * q;
        float2 a = *(const float2*)&g_h0[(size_t)row * DOUT_ + c];
        float2 b = *(const float2*)&g_h1[(size_t)row * DOUT_ + c];
        float2 bb = *(const float2*)&bias[c];
        float x = a.x + b.x + bb.x;
        float y = a.y + b.y + bb.y;
        hx[2 * q] = x; hx[2 * q + 1] = y;
        ss += x * x + y * y;
    }
#pragma unroll
    for (int m = 16; m > 0; m >>= 1)
        ss += __shfl_xor_sync(0xffffffffu, ss, m);
    float inv = 1.0f / fmaxf(sqrtf(ss), 1e-8f);
#pragma unroll
    for (int q = 0; q < 2; q++) {
        int c = 2 * lane + 64 * q;
        *(__nv_bfloat162*)&g_znb[(size_t)row * DOUT_ + c] =
            __floats2bfloat162_rn(hx[2 * q] * inv, hx[2 * q + 1] * inv);
    }
}

// ---------------------------------------------------------------------------
// Kernel 2: sim rowsums via bf16 mma.sync, cp.async double-buffered B.
// Grid (64, 8), 256 thr, 8 warps as 2x4 (warp tile 64x32).
// Smem: A[128][256B] resident + 2 x B[128][256B] stages = 97KB dynamic.
// One barrier per j-tile; B[jt+1] load overlaps compute+epilogue of jt.
// ---------------------------------------------------------------------------
#define SIM_SMEM_BYTES 99328   // 1KB align slack + 3 x 32KB

__global__ __launch_bounds__(256, 2) void sim_rowsum_kernel()
{
    extern __shared__ __align__(16) unsigned char dynsm[];
    const uint32_t smraw = sptr(dynsm);
    const uint32_t smbase = (smraw + 1023) & ~1023u;
    const uint32_t Abase = smbase;
    const uint32_t Bb[2] = {smbase + 32768, smbase + 65536};

    const int tid = threadIdx.x;
    const int lane = tid & 31;
    const int warp = tid >> 5;
    const int wr = warp >> 2;
    const int wc = warp & 3;
    const int i0 = blockIdx.x * 128;
    const int jbase = blockIdx.y * 1024;

    // Load A tile (plain LDG + STS; covered by the first barrier)
#pragma unroll
    for (int it = 0; it < 8; it++) {
        int e = tid + it * 256;
        int r = e >> 4, c = e & 15;
        uint4 v = *(const uint4*)&g_znb[(size_t)(i0 + r) * DOUT_ + c * 8];
        *(uint4*)(dynsm + (Abase - smraw) + r * 256 + ((c ^ (r & 7)) << 4)) = v;
    }

    auto load_B = [&](int jt, int buf) {
#pragma unroll
        for (int it = 0; it < 8; it++) {
            int e = tid + it * 256;
            int r = e >> 4, c = e & 15;
            cpa16(Bb[buf] + r * 256 + ((c ^ (r & 7)) << 4),
                  &g_znb[(size_t)(jbase + jt * 128 + r) * DOUT_ + c * 8]);
        }
        asm volatile("cp.async.commit_group;" ::: "memory");
    };

    load_B(0, 0);

    float rowacc[8];
#pragma unroll
    for (int x = 0; x < 8; x++) rowacc[x] = 0.0f;

    for (int jt = 0; jt < 8; jt++) {
        const int buf = jt & 1;
        asm volatile("cp.async.wait_group 0;" ::: "memory");
        __syncthreads();   // B[jt] visible; all warps done reading buf^1

        if (jt + 1 < 8) load_B(jt + 1, buf ^ 1);

        const int j0 = jbase + jt * 128;
        const uint32_t Bbase = Bb[buf];

        float acc[4][4][4];
#pragma unroll
        for (int mt = 0; mt < 4; mt++)
#pragma unroll
            for (int nt = 0; nt < 4; nt++)
#pragma unroll
                for (int e = 0; e < 4; e++) acc[mt][nt][e] = 0.0f;

#pragma unroll
        for (int sg = 0; sg < 8; sg++) {
            uint32_t a[4][4];
#pragma unroll
            for (int mt = 0; mt < 4; mt++) {
                int rloc = 64 * wr + 16 * mt + (lane & 15);
                int ch = 2 * sg + (lane >> 4);
                uint32_t ad = Abase + rloc * 256 + ((ch ^ (rloc & 7)) << 4);
                ldsm_x4(ad, a[mt][0], a[mt][1], a[mt][2], a[mt][3]);
            }
            uint32_t b[4][2];
#pragma unroll
            for (int p = 0; p < 2; p++) {
                int nloc = 32 * wc + 16 * p + (lane & 7) + ((lane >> 4) << 3);
                int ch = 2 * sg + ((lane >> 3) & 1);
                uint32_t ad = Bbase + nloc * 256 + ((ch ^ (nloc & 7)) << 4);
                ldsm_x4(ad, b[2 * p][0], b[2 * p][1], b[2 * p + 1][0], b[2 * p + 1][1]);
            }
#pragma unroll
            for (int mt = 0; mt < 4; mt++)
#pragma unroll
                for (int nt = 0; nt < 4; nt++)
                    mma16816(acc[mt][nt], a[mt], b[nt]);
        }

        // Epilogue: mask diag, exp-accumulate, capture positives
#pragma unroll
        for (int mt = 0; mt < 4; mt++)
#pragma unroll
            for (int e = 0; e < 4; e++) {
                int row = i0 + 64 * wr + 16 * mt + (lane >> 2) + 8 * (e >> 1);
                int pj = (row + B_) & (N_ - 1);
                float racc = 0.0f;
#pragma unroll
                for (int nt = 0; nt < 4; nt++) {
                    int col = j0 + 32 * wc + 8 * nt + 2 * (lane & 3) + (e & 1);
                    float s = 2.0f * acc[mt][nt][e];   // / temperature
                    if (col != row) racc += __expf(s);
                    if (col == pj) g_pos[row] = s;
                }
                rowacc[mt * 2 + (e >> 1)] += racc;
            }
    }

#pragma unroll
    for (int idx = 0; idx < 8; idx++) {
        float v = rowacc[idx];
        v += __shfl_xor_sync(0xffffffffu, v, 1);
        v += __shfl_xor_sync(0xffffffffu, v, 2);
        if ((lane & 3) == 0) {
            int row = i0 + 64 * wr + 16 * (idx >> 1) + (lane >> 2) + 8 * (idx & 1);
            g_rowsum_part[(blockIdx.y * 4 + wc) * N_ + row] = v;
        }
    }
}

// ---------------------------------------------------------------------------
// Kernel 3a: per-CTA partial loss. 64 CTAs x 256 thr, 128 rows each.
// ---------------------------------------------------------------------------
__global__ __launch_bounds__(256) void finalize_part_kernel()
{
    __shared__ double red[256];
    const int tid = threadIdx.x;
    const int base = blockIdx.x * 128;
    double acc = 0.0;
    {
        int row = base + (tid & 127);
        int half = tid >> 7;           // 0 or 1
        float rs = 0.0f;
#pragma unroll
        for (int p = 0; p < 16; p++)
            rs += g_rowsum_part[(16 * half + p) * N_ + row];
        red[tid] = (double)rs;
    }
    __syncthreads();
    if (tid < 128) {
        int row = base + tid;
        float rs = (float)(red[tid] + red[tid + 128]);
        acc = (double)logf(rs) - (double)g_pos[row];
    }
    __syncthreads();
    red[tid] = (tid < 128) ? acc : 0.0;
    __syncthreads();
    for (int s = 128; s > 0; s >>= 1) {
        if (tid < s) red[tid] += red[tid + s];
        __syncthreads();
    }
    if (tid == 0) g_loss_part[blockIdx.x] = red[0];
}

// ---------------------------------------------------------------------------
// Kernel 3b: sum 64 partials -> loss.
// ---------------------------------------------------------------------------
__global__ __launch_bounds__(64) void finalize_final_kernel(float* __restrict__ out)
{
    const int tid = threadIdx.x;
    double v = g_loss_part[tid];
#pragma unroll
    for (int m = 16; m > 0; m >>= 1)
        v += __shfl_xor_sync(0xffffffffu, v, m);
    __shared__ double wsum[2];
    if ((tid & 31) == 0) wsum[tid >> 5] = v;
    __syncthreads();
    if (tid == 0) out[0] = (float)((wsum[0] + wsum[1]) / (double)N_);
}

// ---------------------------------------------------------------------------
extern "C" void kernel_launch(void* const* d_in, const int* in_sizes, int n_in,
                              void* d_out, int out_size)
{
    const float* zi = (const float*)d_in[0];
    const float* zj = (const float*)d_in[1];
    const float* W  = (const float*)d_in[2];
    const float* b  = (const float*)d_in[3];
    float* out = (float*)d_out;

    static int attr_done = 0;
    if (!attr_done) {
        cudaFuncSetAttribute(gemm1_part_kernel,
                             cudaFuncAttributeMaxDynamicSharedMemorySize,
                             G1_SMEM_BYTES);
        cudaFuncSetAttribute(sim_rowsum_kernel,
                             cudaFuncAttributeMaxDynamicSharedMemorySize,
                             SIM_SMEM_BYTES);
        attr_done = 1;
    }

    wconv_kernel<<<128, 256>>>(W);
    gemm1_part_kernel<<<256, 256, G1_SMEM_BYTES>>>(zi, zj);
    hnorm_kernel<<<1024, 256>>>(b);
    sim_rowsum_kernel<<<dim3(64, 8), 256, SIM_SMEM_BYTES>>>();
    finalize_part_kernel<<<64, 256>>>();
    finalize_final_kernel<<<1, 64>>>(out);
}

// round 14
// speedup vs baseline: 10.2304x; 1.2168x over previous
#include <cuda_runtime.h>
#include <cuda_bf16.h>
#include <math.h>
#include <stdint.h>

// Problem constants
#define B_    4096
#define DIN_  2048
#define DOUT_ 128
#define N_    8192   // 2*B_

// zn pre-scale: dot(zn'_i, zn'_j) = (2/T_temp)*log2(e) * cos_ij  (T=0.5)
// so exp(sim/T) = 2^dot  -- epilogue needs only EX2, no scaling FMULs.
#define ZN_SCALE 1.69864122f    // sqrt(2 * log2(e))
#define LN2_     0.69314718055994531f

// Scratch (device globals -- no allocation allowed)
__device__ __nv_bfloat16 g_znb[N_ * DOUT_];    // scaled normalized reps, bf16
__device__ __nv_bfloat16 g_wb[DOUT_ * DIN_];   // W in bf16, 512 KB
__device__ float g_h0[N_ * DOUT_];             // split-K partial 0, fp32, 4 MB
__device__ float g_h1[N_ * DOUT_];             // split-K partial 1, fp32, 4 MB
__device__ float g_rowsum_part[32 * N_];       // per-(jsplit,warpcol) partials
__device__ float g_pos[N_];                    // positive-pair logits (base-2 units)
__device__ double g_loss_part[64];             // per-CTA partial losses

__device__ __forceinline__ uint32_t sptr(const void* p) {
    return (uint32_t)__cvta_generic_to_shared(p);
}

__device__ __forceinline__ float ex2f(float x) {
    float r;
    asm("ex2.approx.ftz.f32 %0, %1;" : "=f"(r) : "f"(x));
    return r;
}

__device__ __forceinline__ void ldsm_x4(uint32_t addr, uint32_t& r0, uint32_t& r1,
                                        uint32_t& r2, uint32_t& r3) {
    asm volatile("ldmatrix.sync.aligned.m8n8.x4.shared.b16 {%0,%1,%2,%3}, [%4];"
                 : "=r"(r0), "=r"(r1), "=r"(r2), "=r"(r3) : "r"(addr));
}

__device__ __forceinline__ void mma16816(float* c, const uint32_t* a, const uint32_t* b) {
    asm volatile(
        "mma.sync.aligned.m16n8k16.row.col.f32.bf16.bf16.f32 "
        "{%0,%1,%2,%3}, {%4,%5,%6,%7}, {%8,%9}, {%0,%1,%2,%3};"
        : "+f"(c[0]), "+f"(c[1]), "+f"(c[2]), "+f"(c[3])
        : "r"(a[0]), "r"(a[1]), "r"(a[2]), "r"(a[3]), "r"(b[0]), "r"(b[1]));
}

__device__ __forceinline__ void cpa16(uint32_t smem_addr, const void* gptr) {
    asm volatile("cp.async.cg.shared.global.L2::128B [%0], [%1], 16;"
                 :: "r"(smem_addr), "l"(gptr) : "memory");
}

__device__ __forceinline__ void sts16(uint32_t addr, uint4 v) {
    asm volatile("st.shared.v4.b32 [%0], {%1,%2,%3,%4};"
                 :: "r"(addr), "r"(v.x), "r"(v.y), "r"(v.z), "r"(v.w) : "memory");
}

// ---------------------------------------------------------------------------
// Kernel 0: convert W (fp32) -> g_wb (bf16).
// ---------------------------------------------------------------------------
__global__ __launch_bounds__(256) void wconv_kernel(const float* __restrict__ W)
{
    int idx = blockIdx.x * 256 + threadIdx.x;
    const float4* src = (const float4*)W;
    float4 v0 = src[2 * idx];
    float4 v1 = src[2 * idx + 1];
    __nv_bfloat162 h[4];
    h[0] = __floats2bfloat162_rn(v0.x, v0.y);
    h[1] = __floats2bfloat162_rn(v0.z, v0.w);
    h[2] = __floats2bfloat162_rn(v1.x, v1.y);
    h[3] = __floats2bfloat162_rn(v1.z, v1.w);
    *(uint4*)&g_wb[idx * 8] = *(uint4*)h;
}

// ---------------------------------------------------------------------------
// Kernel 1: split-K=2 partial GEMM: Hpart = relu(Z) @ Wb[:, khalf]^T.
// ---------------------------------------------------------------------------
#define G1_SMEM_BYTES 99328

__global__ __launch_bounds__(256, 2) void gemm1_part_kernel(
    const float* __restrict__ zi, const float* __restrict__ zj)
{
    extern __shared__ __align__(16) unsigned char dynsm[];
    const uint32_t smraw = sptr(dynsm);
    const uint32_t smbase = (smraw + 1023) & ~1023u;
    const uint32_t As[2] = {smbase, smbase + 16384};
    const uint32_t Ws[2] = {smbase + 32768, smbase + 65536};

    const int tid = threadIdx.x;
    const int lane = tid & 31;
    const int warp = tid >> 5;
    const int tile = blockIdx.x & 127;
    const int khalf = blockIdx.x >> 7;
    const int kbase = khalf * 8;
    const int i0 = tile * 64;

    const float* Z = (i0 < B_) ? zi : zj;
    const int zr0 = (i0 < B_) ? i0 : (i0 - B_);

    float acc[4][2][4];
#pragma unroll
    for (int mt = 0; mt < 4; mt++)
#pragma unroll
        for (int nt = 0; nt < 2; nt++)
#pragma unroll
            for (int e = 0; e < 4; e++) acc[mt][nt][e] = 0.0f;

    float4 av[8];

    auto fetch_A = [&](int kc) {
#pragma unroll
        for (int it = 0; it < 4; it++) {
            int e = tid + it * 256;
            int r = e >> 4, c = e & 15;
            const float* src = &Z[(size_t)(zr0 + r) * DIN_ + kc * 128 + c * 8];
            av[2 * it]     = *(const float4*)src;
            av[2 * it + 1] = *(const float4*)(src + 4);
        }
    };
    auto store_A = [&](int stg) {
#pragma unroll
        for (int it = 0; it < 4; it++) {
            int e = tid + it * 256;
            int r = e >> 4, c = e & 15;
            float4 v0 = av[2 * it], v1 = av[2 * it + 1];
            __nv_bfloat162 h[4];
            h[0] = __floats2bfloat162_rn(fmaxf(v0.x, 0.f), fmaxf(v0.y, 0.f));
            h[1] = __floats2bfloat162_rn(fmaxf(v0.z, 0.f), fmaxf(v0.w, 0.f));
            h[2] = __floats2bfloat162_rn(fmaxf(v1.x, 0.f), fmaxf(v1.y, 0.f));
            h[3] = __floats2bfloat162_rn(fmaxf(v1.z, 0.f), fmaxf(v1.w, 0.f));
            sts16(As[stg] + r * 256 + ((c ^ (r & 7)) << 4), *(uint4*)h);
        }
    };
    auto load_W = [&](int kc, int stg) {
#pragma unroll
        for (int it = 0; it < 8; it++) {
            int e = tid + it * 256;
            int r = e >> 4, c = e & 15;
            cpa16(Ws[stg] + r * 256 + ((c ^ (r & 7)) << 4),
                  &g_wb[(size_t)r * DIN_ + kc * 128 + c * 8]);
        }
        asm volatile("cp.async.commit_group;" ::: "memory");
    };

    fetch_A(kbase);
    load_W(kbase, 0);
    store_A(0);

    for (int kc2 = 0; kc2 < 8; kc2++) {
        const int stg = kc2 & 1;
        asm volatile("cp.async.wait_group 0;" ::: "memory");
        __syncthreads();

        if (kc2 + 1 < 8) {
            fetch_A(kbase + kc2 + 1);
            load_W(kbase + kc2 + 1, stg ^ 1);
        }

        const uint32_t Abase = As[stg], Wbase = Ws[stg];
#pragma unroll
        for (int s = 0; s < 8; s++) {
            uint32_t a[4][4];
#pragma unroll
            for (int mt = 0; mt < 4; mt++) {
                int rloc = 16 * mt + (lane & 15);
                int ch = 2 * s + (lane >> 4);
                uint32_t ad = Abase + rloc * 256 + ((ch ^ (rloc & 7)) << 4);
                ldsm_x4(ad, a[mt][0], a[mt][1], a[mt][2], a[mt][3]);
            }
            uint32_t b[2][2];
            {
                int nloc = 16 * warp + (lane & 7) + ((lane >> 4) << 3);
                int ch = 2 * s + ((lane >> 3) & 1);
                uint32_t ad = Wbase + nloc * 256 + ((ch ^ (nloc & 7)) << 4);
                ldsm_x4(ad, b[0][0], b[0][1], b[1][0], b[1][1]);
            }
#pragma unroll
            for (int mt = 0; mt < 4; mt++)
#pragma unroll
                for (int nt = 0; nt < 2; nt++)
                    mma16816(acc[mt][nt], a[mt], b[nt]);
        }

        if (kc2 + 1 < 8) store_A(stg ^ 1);
    }

    float* Hp = khalf ? g_h1 : g_h0;
#pragma unroll
    for (int mt = 0; mt < 4; mt++)
#pragma unroll
        for (int nt = 0; nt < 2; nt++) {
            int r0 = i0 + 16 * mt + (lane >> 2);
            int c0 = 16 * warp + 8 * nt + 2 * (lane & 3);
            *(float2*)&Hp[(size_t)r0 * DOUT_ + c0] =
                make_float2(acc[mt][nt][0], acc[mt][nt][1]);
            *(float2*)&Hp[(size_t)(r0 + 8) * DOUT_ + c0] =
                make_float2(acc[mt][nt][2], acc[mt][nt][3]);
        }
}

// ---------------------------------------------------------------------------
// Kernel 1b: combine partials + bias, row-normalize, scale by ZN_SCALE.
// ---------------------------------------------------------------------------
__global__ __launch_bounds__(256) void hnorm_kernel(const float* __restrict__ bias)
{
    const int lane = threadIdx.x & 31;
    const int warp = threadIdx.x >> 5;
    const int row = blockIdx.x * 8 + warp;

    float hx[4];
    float ss = 0.0f;
#pragma unroll
    for (int q = 0; q < 2; q++) {
        int c = 2 * lane + 64 * q;
        float2 a = *(const float2*)&g_h0[(size_t)row * DOUT_ + c];
        float2 b = *(const float2*)&g_h1[(size_t)row * DOUT_ + c];
        float2 bb = *(const float2*)&bias[c];
        float x = a.x + b.x + bb.x;
        float y = a.y + b.y + bb.y;
        hx[2 * q] = x; hx[2 * q + 1] = y;
        ss += x * x + y * y;
    }
#pragma unroll
    for (int m = 16; m > 0; m >>= 1)
        ss += __shfl_xor_sync(0xffffffffu, ss, m);
    float inv = ZN_SCALE / fmaxf(sqrtf(ss), 1e-8f);
#pragma unroll
    for (int q = 0; q < 2; q++) {
        int c = 2 * lane + 64 * q;
        *(__nv_bfloat162*)&g_znb[(size_t)row * DOUT_ + c] =
            __floats2bfloat162_rn(hx[2 * q] * inv, hx[2 * q + 1] * inv);
    }
}

// ---------------------------------------------------------------------------
// Kernel 2: sim rowsums. MMA output t = log2(exp(sim/T)); epilogue is
// EX2+FADD only on fast-path tiles. Diag/pos tiles (CTA-uniform, 128-aligned)
// take the compare path. cp.async addresses hoisted to per-tile const adds.
// ---------------------------------------------------------------------------
#define SIM_SMEM_BYTES 99328   // 1KB align slack + 3 x 32KB

__global__ __launch_bounds__(256, 2) void sim_rowsum_kernel()
{
    extern __shared__ __align__(16) unsigned char dynsm[];
    const uint32_t smraw = sptr(dynsm);
    const uint32_t smbase = (smraw + 1023) & ~1023u;
    const uint32_t Abase = smbase;
    const uint32_t Bb[2] = {smbase + 32768, smbase + 65536};

    const int tid = threadIdx.x;
    const int lane = tid & 31;
    const int warp = tid >> 5;
    const int wr = warp >> 2;
    const int wc = warp & 3;
    const int i0 = blockIdx.x * 128;
    const int jbase = blockIdx.y * 1024;
    const int pos_j0 = (i0 + B_) & (N_ - 1);   // 128-aligned pos-tile start

    // Load A tile (plain LDG + STS; covered by the first barrier)
#pragma unroll
    for (int it = 0; it < 8; it++) {
        int e = tid + it * 256;
        int r = e >> 4, c = e & 15;
        uint4 v = *(const uint4*)&g_znb[(size_t)(i0 + r) * DOUT_ + c * 8];
        *(uint4*)(dynsm + (Abase - smraw) + r * 256 + ((c ^ (r & 7)) << 4)) = v;
    }

    // Hoisted B addressing: per-thread base src/dst; per-it stride constant;
    // swizzle column invariant under r += 16 (r & 7 unchanged).
    const int br = tid >> 4, bc = tid & 15;
    const __nv_bfloat16* srcB0 = &g_znb[(size_t)(jbase + br) * DOUT_ + bc * 8];
    const uint32_t dstoff = (uint32_t)(br * 256 + ((bc ^ (br & 7)) << 4));

    auto load_B = [&](int jt, int buf) {
        const __nv_bfloat16* s = srcB0 + (size_t)jt * (128 * DOUT_);
        uint32_t d = Bb[buf] + dstoff;
#pragma unroll
        for (int it = 0; it < 8; it++) {
            cpa16(d, s);
            s += 16 * DOUT_;   // +16 rows
            d += 16 * 256;     // +16 rows (swizzle-invariant)
        }
        asm volatile("cp.async.commit_group;" ::: "memory");
    };

    load_B(0, 0);

    float rowacc[8];
#pragma unroll
    for (int x = 0; x < 8; x++) rowacc[x] = 0.0f;

    for (int jt = 0; jt < 8; jt++) {
        const int buf = jt & 1;
        asm volatile("cp.async.wait_group 0;" ::: "memory");
        __syncthreads();

        if (jt + 1 < 8) load_B(jt + 1, buf ^ 1);

        const int j0 = jbase + jt * 128;
        const uint32_t Bbase = Bb[buf];

        float acc[4][4][4];
#pragma unroll
        for (int mt = 0; mt < 4; mt++)
#pragma unroll
            for (int nt = 0; nt < 4; nt++)
#pragma unroll
                for (int e = 0; e < 4; e++) acc[mt][nt][e] = 0.0f;

#pragma unroll
        for (int sg = 0; sg < 8; sg++) {
            uint32_t a[4][4];
#pragma unroll
            for (int mt = 0; mt < 4; mt++) {
                int rloc = 64 * wr + 16 * mt + (lane & 15);
                int ch = 2 * sg + (lane >> 4);
                uint32_t ad = Abase + rloc * 256 + ((ch ^ (rloc & 7)) << 4);
                ldsm_x4(ad, a[mt][0], a[mt][1], a[mt][2], a[mt][3]);
            }
            uint32_t b[4][2];
#pragma unroll
            for (int p = 0; p < 2; p++) {
                int nloc = 32 * wc + 16 * p + (lane & 7) + ((lane >> 4) << 3);
                int ch = 2 * sg + ((lane >> 3) & 1);
                uint32_t ad = Bbase + nloc * 256 + ((ch ^ (nloc & 7)) << 4);
                ldsm_x4(ad, b[2 * p][0], b[2 * p][1], b[2 * p + 1][0], b[2 * p + 1][1]);
            }
#pragma unroll
            for (int mt = 0; mt < 4; mt++)
#pragma unroll
                for (int nt = 0; nt < 4; nt++)
                    mma16816(acc[mt][nt], a[mt], b[nt]);
        }

        // Epilogue
        if (j0 != i0 && j0 != pos_j0) {
            // FAST PATH: no compares, pure EX2 + FADD.
#pragma unroll
            for (int mt = 0; mt < 4; mt++)
#pragma unroll
                for (int e = 0; e < 4; e++) {
                    float racc = 0.0f;
#pragma unroll
                    for (int nt = 0; nt < 4; nt++)
                        racc += ex2f(acc[mt][nt][e]);
                    rowacc[mt * 2 + (e >> 1)] += racc;
                }
        } else {
            const bool isdiag = (j0 == i0);
#pragma unroll
            for (int mt = 0; mt < 4; mt++)
#pragma unroll
                for (int e = 0; e < 4; e++) {
                    int row = i0 + 64 * wr + 16 * mt + (lane >> 2) + 8 * (e >> 1);
                    int special = isdiag ? row : ((row + B_) & (N_ - 1));
                    float racc = 0.0f;
#pragma unroll
                    for (int nt = 0; nt < 4; nt++) {
                        int col = j0 + 32 * wc + 8 * nt + 2 * (lane & 3) + (e & 1);
                        float t = acc[mt][nt][e];
                        if (isdiag) {
                            if (col != row) racc += ex2f(t);
                        } else {
                            racc += ex2f(t);
                            if (col == special) g_pos[row] = t;
                        }
                    }
                    rowacc[mt * 2 + (e >> 1)] += racc;
                }
        }
    }

#pragma unroll
    for (int idx = 0; idx < 8; idx++) {
        float v = rowacc[idx];
        v += __shfl_xor_sync(0xffffffffu, v, 1);
        v += __shfl_xor_sync(0xffffffffu, v, 2);
        if ((lane & 3) == 0) {
            int row = i0 + 64 * wr + 16 * (idx >> 1) + (lane >> 2) + 8 * (idx & 1);
            g_rowsum_part[(blockIdx.y * 4 + wc) * N_ + row] = v;
        }
    }
}

// ---------------------------------------------------------------------------
// Kernel 3a: per-CTA partial loss. pos is in base-2 units -> multiply by ln2.
// ---------------------------------------------------------------------------
__global__ __launch_bounds__(256) void finalize_part_kernel()
{
    __shared__ double red[256];
    const int tid = threadIdx.x;
    const int base = blockIdx.x * 128;
    double acc = 0.0;
    {
        int row = base + (tid & 127);
        int half = tid >> 7;
        float rs = 0.0f;
#pragma unroll
        for (int p = 0; p < 16; p++)
            rs += g_rowsum_part[(16 * half + p) * N_ + row];
        red[tid] = (double)rs;
    }
    __syncthreads();
    if (tid < 128) {
        int row = base + tid;
        float rs = (float)(red[tid] + red[tid + 128]);
        acc = (double)logf(rs) - (double)(g_pos[row] * LN2_);
    }
    __syncthreads();
    red[tid] = (tid < 128) ? acc : 0.0;
    __syncthreads();
    for (int s = 128; s > 0; s >>= 1) {
        if (tid < s) red[tid] += red[tid + s];
        __syncthreads();
    }
    if (tid == 0) g_loss_part[blockIdx.x] = red[0];
}

// ---------------------------------------------------------------------------
// Kernel 3b: sum 64 partials -> loss.
// ---------------------------------------------------------------------------
__global__ __launch_bounds__(64) void finalize_final_kernel(float* __restrict__ out)
{
    const int tid = threadIdx.x;
    double v = g_loss_part[tid];
#pragma unroll
    for (int m = 16; m > 0; m >>= 1)
        v += __shfl_xor_sync(0xffffffffu, v, m);
    __shared__ double wsum[2];
    if ((tid & 31) == 0) wsum[tid >> 5] = v;
    __syncthreads();
    if (tid == 0) out[0] = (float)((wsum[0] + wsum[1]) / (double)N_);
}

// ---------------------------------------------------------------------------
extern "C" void kernel_launch(void* const* d_in, const int* in_sizes, int n_in,
                              void* d_out, int out_size)
{
    const float* zi = (const float*)d_in[0];
    const float* zj = (const float*)d_in[1];
    const float* W  = (const float*)d_in[2];
    const float* b  = (const float*)d_in[3];
    float* out = (float*)d_out;

    static int attr_done = 0;
    if (!attr_done) {
        cudaFuncSetAttribute(gemm1_part_kernel,
                             cudaFuncAttributeMaxDynamicSharedMemorySize,
                             G1_SMEM_BYTES);
        cudaFuncSetAttribute(sim_rowsum_kernel,
                             cudaFuncAttributeMaxDynamicSharedMemorySize,
                             SIM_SMEM_BYTES);
        attr_done = 1;
    }

    wconv_kernel<<<128, 256>>>(W);
    gemm1_part_kernel<<<256, 256, G1_SMEM_BYTES>>>(zi, zj);
    hnorm_kernel<<<1024, 256>>>(b);
    sim_rowsum_kernel<<<dim3(64, 8), 256, SIM_SMEM_BYTES>>>();
    finalize_part_kernel<<<64, 256>>>();
    finalize_final_kernel<<<1, 64>>>(out);
}